// round 3
// baseline (speedup 1.0000x reference)
#include <cuda_runtime.h>
#include <math.h>

// ---------------- problem constants ----------------
constexpr int B = 2, V = 3, G = 2, NH = 8, C = 128;
constexpr int CPG = C / G;       // 64
constexpr int CH  = C / NH;      // 16
constexpr int HPG = NH / G;      // 4
constexpr int Hq = 32, Wq = 32, M = Hq * Wq;   // 1024
constexpr int D = 4;
constexpr int Hk = Hq / 2, Wk = Wq * D;        // 16, 128
constexpr int NS = Hk * Wk;                    // 2048
constexpr int Hi = 64, Wi = 64;
constexpr int RH = Hq * 2 - 1;   // 63
constexpr int RW = Wq * D * 2 - 1; // 255
constexpr float SCALE = 0.25f;   // CH^-0.5
constexpr float OFR = 5.0f;
constexpr float EPS = 1e-5f;

// ---------------- scratch (static device globals; no allocation) -------------
__device__ float g_rwo[V][B * G][NS][2];   // [n][0]=y-comp (p=0), [n][1]=x-comp (p=1)
__device__ float g_xs[V][B][C][NS];
__device__ float g_k[V][B][C][NS];
__device__ float g_v[V][B][C][NS];
__device__ float g_outcat[B][V * C][M];

// =====================================================================
// Kernel 1: offset net. ONE THREAD PER PIXEL. Zero warp communication.
// h[c*4+d] = q_g[c]*w1[c*4+d]+b1[c*4+d]; LN(256); exact GELU; po[d]=sum w2[d,:]*ge
// g_rwo[hk*Wk + x*4+d][p=y&1] = tanh(po[d])*OFR*rng[p] + refpts[...,1-p]
// =====================================================================
__global__ __launch_bounds__(256) void k_offset(
    const float* __restrict__ query,
    const float* __restrict__ refpts,   // (B,V,Hk,Wk,2)
    const float* __restrict__ w1,       // (V,256)
    const float* __restrict__ b1,
    const float* __restrict__ lng,
    const float* __restrict__ lnb,
    const float* __restrict__ w2)       // (V,4,256)
{
    int pix = blockIdx.x * 256 + threadIdx.x;   // 0..1023
    int bg = blockIdx.y, vi = blockIdx.z;
    int b = bg / G, g = bg % G;
    int y = pix >> 5, x = pix & 31;

    const float* W1 = w1 + vi * 256;
    const float* B1 = b1 + vi * 256;
    const float* LG = lng + vi * 256;
    const float* LB = lnb + vi * 256;
    const float* W2 = w2 + vi * 4 * 256;

    // pass 1: mean / var over the 256 intermediate channels
    float s = 0.f, ss = 0.f;
    for (int c = 0; c < CPG; c++) {
        float qv = query[((b * C + g * CPG + c) * Hq + y) * Wq + x];
#pragma unroll
        for (int d = 0; d < 4; d++) {
            int cd = c * 4 + d;
            float hv = qv * W1[cd] + B1[cd];
            s += hv; ss += hv * hv;
        }
    }
    float mu  = s * (1.f / 256.f);
    float var = ss * (1.f / 256.f) - mu * mu;
    float rs  = rsqrtf(var + EPS);

    // pass 2: LN -> GELU -> 1x1 conv (4 outputs)
    float po[4] = {0.f, 0.f, 0.f, 0.f};
    for (int c = 0; c < CPG; c++) {
        float qv = query[((b * C + g * CPG + c) * Hq + y) * Wq + x];
#pragma unroll
        for (int d = 0; d < 4; d++) {
            int cd = c * 4 + d;
            float hv = qv * W1[cd] + B1[cd];
            float hn = (hv - mu) * rs * LG[cd] + LB[cd];
            float ge = 0.5f * hn * (1.f + erff(hn * 0.70710678118654752f));
#pragma unroll
            for (int d2 = 0; d2 < 4; d2++)
                po[d2] += ge * W2[d2 * 256 + cd];
        }
    }

    int p = y & 1, hk = y >> 1;
    float scl = (p == 0) ? (OFR / (float)(Hk - 1)) : (OFR / (float)(Wk - 1));
#pragma unroll
    for (int d = 0; d < 4; d++) {
        int wk = x * 4 + d;
        float rv = refpts[(((b * V + vi) * Hk + hk) * Wk + wk) * 2 + (1 - p)];
        g_rwo[vi][bg][hk * Wk + wk][p] = tanhf(po[d]) * scl + rv;
    }
}

// =====================================================================
// Kernel 2: bilinear grid-sample of x at rwo. ONE THREAD per (n, channel).
// y-pixel from rwo[...,0], x-pixel from rwo[...,1] (grid is rwo[...,::-1]).
// =====================================================================
__global__ __launch_bounds__(256) void k_sample(const float* __restrict__ x)
{
    int cc = threadIdx.x & 63;          // channel within group
    int nsub = threadIdx.x >> 6;        // 0..3
    int n = blockIdx.x * 4 + nsub;      // 0..2047
    int bg = blockIdx.y, vi = blockIdx.z;
    int b = bg / G, g = bg % G;

    float r0 = g_rwo[vi][bg][n][0];     // y in [-1,1]
    float r1 = g_rwo[vi][bg][n][1];     // x in [-1,1]
    float yp = (r0 + 1.f) * 0.5f * (float)(Hi - 1);
    float xp = (r1 + 1.f) * 0.5f * (float)(Wi - 1);
    float y0f = floorf(yp), x0f = floorf(xp);
    float fy = yp - y0f, fx = xp - x0f;
    int y0 = (int)y0f, x0 = (int)x0f;

    float wy0 = (y0     >= 0 && y0     <= Hi - 1) ? (1.f - fy) : 0.f;
    float wy1 = (y0 + 1 >= 0 && y0 + 1 <= Hi - 1) ? fy         : 0.f;
    float wx0 = (x0     >= 0 && x0     <= Wi - 1) ? (1.f - fx) : 0.f;
    float wx1 = (x0 + 1 >= 0 && x0 + 1 <= Wi - 1) ? fx         : 0.f;
    int iy0 = min(max(y0, 0), Hi - 1), iy1 = min(max(y0 + 1, 0), Hi - 1);
    int ix0 = min(max(x0, 0), Wi - 1), ix1 = min(max(x0 + 1, 0), Wi - 1);

    const float* img = x + (size_t)((b * V + vi) * C + g * CPG + cc) * (Hi * Wi);
    float val = wy0 * wx0 * img[iy0 * Wi + ix0]
              + wy0 * wx1 * img[iy0 * Wi + ix1]
              + wy1 * wx0 * img[iy1 * Wi + ix0]
              + wy1 * wx1 * img[iy1 * Wi + ix1];
    g_xs[vi][b][g * CPG + cc][n] = val;
}

// =====================================================================
// Kernel 3: K/V projection: out[o,n] = sum_c w[o,c]*xs[c,n] + bias[o]
// =====================================================================
__global__ __launch_bounds__(256) void k_proj(
    const float* __restrict__ kw, const float* __restrict__ kb,
    const float* __restrict__ vw, const float* __restrict__ vb)
{
    int n  = blockIdx.x * 256 + threadIdx.x;    // 0..2047
    int o0 = blockIdx.y * 8;                    // 0..120
    int z  = blockIdx.z;                        // 12
    int kv = z & 1, b = (z >> 1) & 1, vi = z >> 2;
    const float* w    = kv ? vw : kw;
    const float* bias = kv ? vb : kb;

    __shared__ float sW[8][C];
    for (int idx = threadIdx.x; idx < 8 * C; idx += 256)
        sW[idx >> 7][idx & 127] = w[(o0 + (idx >> 7)) * C + (idx & 127)];
    __syncthreads();

    float acc[8];
#pragma unroll
    for (int oo = 0; oo < 8; oo++) acc[oo] = bias[o0 + oo];

    const float* xs = &g_xs[vi][b][0][0];
    for (int c = 0; c < C; c++) {
        float xv = xs[c * NS + n];
#pragma unroll
        for (int oo = 0; oo < 8; oo++) acc[oo] += sW[oo][c] * xv;
    }
    float* dst = kv ? &g_v[vi][b][0][0] : &g_k[vi][b][0][0];
#pragma unroll
    for (int oo = 0; oo < 8; oo++) dst[(o0 + oo) * NS + n] = acc[oo];
}

// =====================================================================
// Kernel 4: attention. Warp per query m. Each LANE keeps a PRIVATE online
// softmax over its own n subset (n % 32 == lane); single reduction at end.
// No cross-lane communication inside the hot loop.
// =====================================================================
__global__ __launch_bounds__(256) void k_attn(
    const float* __restrict__ query,
    const float* __restrict__ rpe_table)
{
    int warp = threadIdx.x >> 5, lane = threadIdx.x & 31, tid = threadIdx.x;
    int vi = blockIdx.z;
    int bh = blockIdx.y;
    int b = bh / NH, h = bh % NH;
    int g = h / HPG;
    int bg = b * G + g;
    int m = blockIdx.x * 8 + warp;
    int i = m >> 5, j = m & 31;

    __shared__ float sK[CH][256];
    __shared__ float sV[CH][256];
    __shared__ float sR[256][2];

    float qreg[CH];
#pragma unroll
    for (int c = 0; c < CH; c++)
        qreg[c] = query[(b * C + h * CH + c) * M + m];

    const float* rpe = rpe_table + h * RH * RW;
    const float* kbase = &g_k[vi][b][h * CH][0];
    const float* vbase = &g_v[vi][b][h * CH][0];

    // per-lane private online softmax state
    float mloc = -1e30f, lloc = 0.f;
    float acc[CH];
#pragma unroll
    for (int c = 0; c < CH; c++) acc[c] = 0.f;

    // rpe pixel coords: yp = 15.5 + i - 15.5*rwo0 ; xp = 63.5 + (127/31)*j - 63.5*rwo1
    float ybase = 15.5f + (float)i;
    float xbase = 63.5f + (127.0f / 31.0f) * (float)j;

    for (int t = 0; t < NS / 256; t++) {
        __syncthreads();
        for (int idx = tid; idx < CH * 64; idx += 256) {
            int c = idx >> 6, n4 = idx & 63;
            ((float4*)sK[c])[n4] = ((const float4*)(kbase + c * NS + t * 256))[n4];
            ((float4*)sV[c])[n4] = ((const float4*)(vbase + c * NS + t * 256))[n4];
        }
        for (int idx = tid; idx < 128; idx += 256)
            ((float4*)sR)[idx] = ((const float4*)&g_rwo[vi][bg][t * 256][0])[idx];
        __syncthreads();

#pragma unroll 1
        for (int ch = 0; ch < 8; ch++) {
            int nl = ch * 32 + lane;
            float s = 0.f;
#pragma unroll
            for (int c = 0; c < CH; c++) s += qreg[c] * sK[c][nl];
            s *= SCALE;

            float r0 = sR[nl][0], r1 = sR[nl][1];
            float yp = ybase - 15.5f * r0;
            float xp = xbase - 63.5f * r1;
            float y0f = floorf(yp), x0f = floorf(xp);
            float fy = yp - y0f, fx = xp - x0f;
            int y0 = (int)y0f, x0 = (int)x0f;

            float wy0 = (y0     >= 0 && y0     <= RH - 1) ? (1.f - fy) : 0.f;
            float wy1 = (y0 + 1 >= 0 && y0 + 1 <= RH - 1) ? fy         : 0.f;
            float wx0 = (x0     >= 0 && x0     <= RW - 1) ? (1.f - fx) : 0.f;
            float wx1 = (x0 + 1 >= 0 && x0 + 1 <= RW - 1) ? fx         : 0.f;
            int iy0 = min(max(y0, 0), RH - 1), iy1 = min(max(y0 + 1, 0), RH - 1);
            int ix0 = min(max(x0, 0), RW - 1), ix1 = min(max(x0 + 1, 0), RW - 1);

            const float* row0 = rpe + iy0 * RW;
            const float* row1 = rpe + iy1 * RW;
            s += wy0 * (wx0 * row0[ix0] + wx1 * row0[ix1])
               + wy1 * (wx0 * row1[ix0] + wx1 * row1[ix1]);

            // per-lane online softmax
            if (s > mloc) {
                float sc = __expf(mloc - s);
                lloc *= sc;
#pragma unroll
                for (int c = 0; c < CH; c++) acc[c] *= sc;
                mloc = s;
            }
            float p = __expf(s - mloc);
            lloc += p;
#pragma unroll
            for (int c = 0; c < CH; c++) acc[c] += p * sV[c][nl];
        }
    }

    // cross-lane: global max, rescale local sums, reduce
    float gmax = mloc;
#pragma unroll
    for (int o = 16; o; o >>= 1)
        gmax = fmaxf(gmax, __shfl_xor_sync(0xffffffffu, gmax, o));
    float f = __expf(mloc - gmax);
    float lsum = lloc * f;
#pragma unroll
    for (int o = 16; o; o >>= 1)
        lsum += __shfl_xor_sync(0xffffffffu, lsum, o);
    float inv = 1.f / lsum;

#pragma unroll
    for (int c = 0; c < CH; c++) {
        float o = acc[c] * f;
#pragma unroll
        for (int q = 16; q; q >>= 1)
            o += __shfl_xor_sync(0xffffffffu, o, q);
        if (lane == 0)
            g_outcat[b][vi * C + h * CH + c][m] = o * inv;
    }
}

// =====================================================================
// Kernel 5: output projection: out = out_w (128x384) @ outcat + out_b
// =====================================================================
__global__ __launch_bounds__(256) void k_out(
    const float* __restrict__ ow, const float* __restrict__ ob,
    float* __restrict__ out)
{
    int mm = blockIdx.x * 256 + threadIdx.x;    // 0..1023
    int o0 = blockIdx.y * 8;
    int b  = blockIdx.z;

    __shared__ float sW[8][V * C];  // 12KB
    for (int idx = threadIdx.x; idx < 8 * V * C; idx += 256)
        sW[idx / (V * C)][idx % (V * C)] = ow[(o0 + idx / (V * C)) * (V * C) + (idx % (V * C))];
    __syncthreads();

    float acc[8];
#pragma unroll
    for (int oo = 0; oo < 8; oo++) acc[oo] = ob[o0 + oo];

    const float* src = &g_outcat[b][0][0];
    for (int c = 0; c < V * C; c++) {
        float xv = src[c * M + mm];
#pragma unroll
        for (int oo = 0; oo < 8; oo++) acc[oo] += sW[oo][c] * xv;
    }
#pragma unroll
    for (int oo = 0; oo < 8; oo++)
        out[(b * C + o0 + oo) * M + mm] = acc[oo];
}

// =====================================================================
extern "C" void kernel_launch(void* const* d_in, const int* in_sizes, int n_in,
                              void* d_out, int out_size)
{
    // Resolve input pointers by size signature.
    // Dict order (setup_inputs insertion order): x(3145728), query(262144),
    // reference_points(24576), off_w1(768), off_b1(768), off_ln_g(768),
    // off_ln_b(768), off_w2(3072), k_w(16384), k_b(128), v_w(16384), v_b(128),
    // out_w(49152), out_b(128), rpe_table(128520)
    const float *x, *query, *refpts, *off_w1, *off_b1, *off_ln_g, *off_ln_b,
                *off_w2, *k_w, *k_b, *v_w, *v_b, *out_w, *out_b, *rpe;

    if (n_in >= 15 && in_sizes[0] == 3145728) {
        // dict order
        x        = (const float*)d_in[0];
        query    = (const float*)d_in[1];
        refpts   = (const float*)d_in[2];
        off_w1   = (const float*)d_in[3];
        off_b1   = (const float*)d_in[4];
        off_ln_g = (const float*)d_in[5];
        off_ln_b = (const float*)d_in[6];
        off_w2   = (const float*)d_in[7];
        k_w      = (const float*)d_in[8];
        k_b      = (const float*)d_in[9];
        v_w      = (const float*)d_in[10];
        v_b      = (const float*)d_in[11];
        out_w    = (const float*)d_in[12];
        out_b    = (const float*)d_in[13];
        rpe      = (const float*)d_in[14];
    } else {
        // alphabetical: k_b, k_w, off_b1, off_ln_b, off_ln_g, off_w1, off_w2,
        //               out_b, out_w, query, reference_points, rpe_table,
        //               v_b, v_w, x
        k_b      = (const float*)d_in[0];
        k_w      = (const float*)d_in[1];
        off_b1   = (const float*)d_in[2];
        off_ln_b = (const float*)d_in[3];
        off_ln_g = (const float*)d_in[4];
        off_w1   = (const float*)d_in[5];
        off_w2   = (const float*)d_in[6];
        out_b    = (const float*)d_in[7];
        out_w    = (const float*)d_in[8];
        query    = (const float*)d_in[9];
        refpts   = (const float*)d_in[10];
        rpe      = (const float*)d_in[11];
        v_b      = (const float*)d_in[12];
        v_w      = (const float*)d_in[13];
        x        = (const float*)d_in[14];
    }
    float* out = (float*)d_out;

    k_offset<<<dim3(M / 256, B * G, V), 256>>>(query, refpts, off_w1, off_b1,
                                               off_ln_g, off_ln_b, off_w2);
    k_sample<<<dim3(NS / 4, B * G, V), 256>>>(x);
    k_proj<<<dim3(NS / 256, C / 8, V * B * 2), 256>>>(k_w, k_b, v_w, v_b);
    k_attn<<<dim3(M / 8, B * NH, V), 256>>>(query, rpe);
    k_out<<<dim3(M / 256, C / 8, B), 256>>>(out_w, out_b, out);
}

// round 4
// speedup vs baseline: 1.2312x; 1.2312x over previous
#include <cuda_runtime.h>
#include <math.h>

// ---------------- problem constants ----------------
constexpr int B = 2, V = 3, G = 2, NH = 8, C = 128;
constexpr int CPG = C / G;       // 64
constexpr int CH  = C / NH;      // 16
constexpr int HPG = NH / G;      // 4
constexpr int Hq = 32, Wq = 32, M = Hq * Wq;   // 1024
constexpr int D = 4;
constexpr int Hk = Hq / 2, Wk = Wq * D;        // 16, 128
constexpr int NS = Hk * Wk;                    // 2048
constexpr int Hi = 64, Wi = 64;
constexpr int RH = Hq * 2 - 1;   // 63
constexpr int RW = Wq * D * 2 - 1; // 255
constexpr float SCALE = 0.25f;   // CH^-0.5
constexpr float OFR = 5.0f;
constexpr float EPS = 1e-5f;

// ---------------- scratch (static device globals; no allocation) -------------
__device__ float g_rwo[V][B * G][NS][2];   // [n][0]=y-comp, [n][1]=x-comp
__device__ float g_xs[V][B][C][NS];
__device__ float g_k[V][B][C][NS];
__device__ float g_v[V][B][C][NS];
__device__ float g_outcat[B][V * C][M];

// =====================================================================
// Kernel 1: offset net. ONE THREAD PER PIXEL. (unchanged — correct)
// =====================================================================
__global__ __launch_bounds__(256) void k_offset(
    const float* __restrict__ query,
    const float* __restrict__ refpts,   // (B,V,Hk,Wk,2)
    const float* __restrict__ w1,       // (V,256)
    const float* __restrict__ b1,
    const float* __restrict__ lng,
    const float* __restrict__ lnb,
    const float* __restrict__ w2)       // (V,4,256)
{
    int pix = blockIdx.x * 256 + threadIdx.x;   // 0..1023
    int bg = blockIdx.y, vi = blockIdx.z;
    int b = bg / G, g = bg % G;
    int y = pix >> 5, x = pix & 31;

    const float* W1 = w1 + vi * 256;
    const float* B1 = b1 + vi * 256;
    const float* LG = lng + vi * 256;
    const float* LB = lnb + vi * 256;
    const float* W2 = w2 + vi * 4 * 256;

    float s = 0.f, ss = 0.f;
    for (int c = 0; c < CPG; c++) {
        float qv = query[((b * C + g * CPG + c) * Hq + y) * Wq + x];
#pragma unroll
        for (int d = 0; d < 4; d++) {
            int cd = c * 4 + d;
            float hv = qv * W1[cd] + B1[cd];
            s += hv; ss += hv * hv;
        }
    }
    float mu  = s * (1.f / 256.f);
    float var = ss * (1.f / 256.f) - mu * mu;
    float rs  = rsqrtf(var + EPS);

    float po[4] = {0.f, 0.f, 0.f, 0.f};
    for (int c = 0; c < CPG; c++) {
        float qv = query[((b * C + g * CPG + c) * Hq + y) * Wq + x];
#pragma unroll
        for (int d = 0; d < 4; d++) {
            int cd = c * 4 + d;
            float hv = qv * W1[cd] + B1[cd];
            float hn = (hv - mu) * rs * LG[cd] + LB[cd];
            float ge = 0.5f * hn * (1.f + erff(hn * 0.70710678118654752f));
#pragma unroll
            for (int d2 = 0; d2 < 4; d2++)
                po[d2] += ge * W2[d2 * 256 + cd];
        }
    }

    int p = y & 1, hk = y >> 1;
    float scl = (p == 0) ? (OFR / (float)(Hk - 1)) : (OFR / (float)(Wk - 1));
#pragma unroll
    for (int d = 0; d < 4; d++) {
        int wk = x * 4 + d;
        float rv = refpts[(((b * V + vi) * Hk + hk) * Wk + wk) * 2 + (1 - p)];
        g_rwo[vi][bg][hk * Wk + wk][p] = tanhf(po[d]) * scl + rv;
    }
}

// =====================================================================
// Kernel 2: bilinear grid-sample of x. ONE THREAD per (n, channel). (unchanged)
// =====================================================================
__global__ __launch_bounds__(256) void k_sample(const float* __restrict__ x)
{
    int cc = threadIdx.x & 63;
    int nsub = threadIdx.x >> 6;
    int n = blockIdx.x * 4 + nsub;
    int bg = blockIdx.y, vi = blockIdx.z;
    int b = bg / G, g = bg % G;

    float r0 = g_rwo[vi][bg][n][0];
    float r1 = g_rwo[vi][bg][n][1];
    float yp = (r0 + 1.f) * 0.5f * (float)(Hi - 1);
    float xp = (r1 + 1.f) * 0.5f * (float)(Wi - 1);
    float y0f = floorf(yp), x0f = floorf(xp);
    float fy = yp - y0f, fx = xp - x0f;
    int y0 = (int)y0f, x0 = (int)x0f;

    float wy0 = (y0     >= 0 && y0     <= Hi - 1) ? (1.f - fy) : 0.f;
    float wy1 = (y0 + 1 >= 0 && y0 + 1 <= Hi - 1) ? fy         : 0.f;
    float wx0 = (x0     >= 0 && x0     <= Wi - 1) ? (1.f - fx) : 0.f;
    float wx1 = (x0 + 1 >= 0 && x0 + 1 <= Wi - 1) ? fx         : 0.f;
    int iy0 = min(max(y0, 0), Hi - 1), iy1 = min(max(y0 + 1, 0), Hi - 1);
    int ix0 = min(max(x0, 0), Wi - 1), ix1 = min(max(x0 + 1, 0), Wi - 1);

    const float* img = x + (size_t)((b * V + vi) * C + g * CPG + cc) * (Hi * Wi);
    float val = wy0 * wx0 * img[iy0 * Wi + ix0]
              + wy0 * wx1 * img[iy0 * Wi + ix1]
              + wy1 * wx0 * img[iy1 * Wi + ix0]
              + wy1 * wx1 * img[iy1 * Wi + ix1];
    g_xs[vi][b][g * CPG + cc][n] = val;
}

// =====================================================================
// Kernel 3: K/V projection (unchanged)
// =====================================================================
__global__ __launch_bounds__(256) void k_proj(
    const float* __restrict__ kw, const float* __restrict__ kb,
    const float* __restrict__ vw, const float* __restrict__ vb)
{
    int n  = blockIdx.x * 256 + threadIdx.x;
    int o0 = blockIdx.y * 8;
    int z  = blockIdx.z;
    int kv = z & 1, b = (z >> 1) & 1, vi = z >> 2;
    const float* w    = kv ? vw : kw;
    const float* bias = kv ? vb : kb;

    __shared__ float sW[8][C];
    for (int idx = threadIdx.x; idx < 8 * C; idx += 256)
        sW[idx >> 7][idx & 127] = w[(o0 + (idx >> 7)) * C + (idx & 127)];
    __syncthreads();

    float acc[8];
#pragma unroll
    for (int oo = 0; oo < 8; oo++) acc[oo] = bias[o0 + oo];

    const float* xs = &g_xs[vi][b][0][0];
    for (int c = 0; c < C; c++) {
        float xv = xs[c * NS + n];
#pragma unroll
        for (int oo = 0; oo < 8; oo++) acc[oo] += sW[oo][c] * xv;
    }
    float* dst = kv ? &g_v[vi][b][0][0] : &g_k[vi][b][0][0];
#pragma unroll
    for (int oo = 0; oo < 8; oo++) dst[(o0 + oo) * NS + n] = acc[oo];
}

// =====================================================================
// Kernel 4: attention, 2-QUERY TILING. Warp handles queries (i0,j) and
// (i0+1,j): K/V/R shared-memory reads amortized x2; rpe bilinear shares
// 3 rows (6 gathers) between the pair. Lane-private online softmax.
// =====================================================================
__global__ __launch_bounds__(256) void k_attn(
    const float* __restrict__ query,
    const float* __restrict__ rpe_table)
{
    int warp = threadIdx.x >> 5, lane = threadIdx.x & 31, tid = threadIdx.x;
    int vi = blockIdx.z;
    int bh = blockIdx.y;
    int b = bh / NH, h = bh % NH;
    int g = h / HPG;
    int bg = b * G + g;

    int mp = blockIdx.x * 8 + warp;      // pair index 0..511
    int i0 = (mp >> 5) * 2;              // even row
    int j  = mp & 31;
    int m0 = i0 * 32 + j;
    int m1 = m0 + 32;

    __shared__ float sK[CH][256];
    __shared__ float sV[CH][256];
    __shared__ float sR0[256];
    __shared__ float sR1[256];

    float q0[CH], q1[CH];
#pragma unroll
    for (int c = 0; c < CH; c++) {
        q0[c] = query[(b * C + h * CH + c) * M + m0];
        q1[c] = query[(b * C + h * CH + c) * M + m1];
    }

    const float* rpe = rpe_table + h * RH * RW;
    const float* kbase = &g_k[vi][b][h * CH][0];
    const float* vbase = &g_v[vi][b][h * CH][0];

    float ml0 = -1e30f, ll0 = 0.f, ml1 = -1e30f, ll1 = 0.f;
    float acc0[CH], acc1[CH];
#pragma unroll
    for (int c = 0; c < CH; c++) { acc0[c] = 0.f; acc1[c] = 0.f; }

    float ybase = 15.5f + (float)i0;
    float xbase = 63.5f + (127.0f / 31.0f) * (float)j;

    for (int t = 0; t < NS / 256; t++) {
        __syncthreads();
        for (int idx = tid; idx < CH * 64; idx += 256) {
            int c = idx >> 6, n4 = idx & 63;
            ((float4*)sK[c])[n4] = ((const float4*)(kbase + c * NS + t * 256))[n4];
            ((float4*)sV[c])[n4] = ((const float4*)(vbase + c * NS + t * 256))[n4];
        }
        {
            float2 rv = ((const float2*)&g_rwo[vi][bg][t * 256][0])[tid];
            sR0[tid] = rv.x;
            sR1[tid] = rv.y;
        }
        __syncthreads();

#pragma unroll 1
        for (int ch = 0; ch < 8; ch++) {
            int nl = ch * 32 + lane;
            float s0 = 0.f, s1 = 0.f;
#pragma unroll
            for (int c = 0; c < CH; c++) {
                float kc = sK[c][nl];
                s0 += q0[c] * kc;
                s1 += q1[c] * kc;
            }

            // --- shared bilinear rpe for the query pair ---
            float r0v = sR0[nl], r1v = sR1[nl];
            float xp = xbase - 63.5f * r1v;
            float x0f = floorf(xp);
            float fx = xp - x0f;
            int x0 = (int)x0f;
            float wx0 = (x0     >= 0 && x0     <= RW - 1) ? (1.f - fx) : 0.f;
            float wx1 = (x0 + 1 >= 0 && x0 + 1 <= RW - 1) ? fx         : 0.f;
            int ix0 = min(max(x0, 0), RW - 1), ix1 = min(max(x0 + 1, 0), RW - 1);

            float yp = ybase - 15.5f * r0v;        // y-pixel for query m0
            float y0f = floorf(yp);
            float fy = yp - y0f;
            int y0 = (int)y0f;                     // rows y0, y0+1, y0+2
            bool v0 = (y0     >= 0) && (y0     <= RH - 1);
            bool v1 = (y0 + 1 >= 0) && (y0 + 1 <= RH - 1);
            bool v2 = (y0 + 2 >= 0) && (y0 + 2 <= RH - 1);
            int cr0 = min(max(y0,     0), RH - 1);
            int cr1 = min(max(y0 + 1, 0), RH - 1);
            int cr2 = min(max(y0 + 2, 0), RH - 1);

            const float* p0r = rpe + cr0 * RW;
            const float* p1r = rpe + cr1 * RW;
            const float* p2r = rpe + cr2 * RW;
            float rc0 = wx0 * p0r[ix0] + wx1 * p0r[ix1];
            float rc1 = wx0 * p1r[ix0] + wx1 * p1r[ix1];
            float rc2 = wx0 * p2r[ix0] + wx1 * p2r[ix1];

            float wyA0 = v0 ? (1.f - fy) : 0.f;
            float wyA1 = v1 ? fy         : 0.f;
            float wyB0 = v1 ? (1.f - fy) : 0.f;
            float wyB1 = v2 ? fy         : 0.f;

            s0 = s0 * SCALE + wyA0 * rc0 + wyA1 * rc1;
            s1 = s1 * SCALE + wyB0 * rc1 + wyB1 * rc2;

            // --- per-lane online softmax, query 0 ---
            if (s0 > ml0) {
                float sc = __expf(ml0 - s0);
                ll0 *= sc;
#pragma unroll
                for (int c = 0; c < CH; c++) acc0[c] *= sc;
                ml0 = s0;
            }
            float p0 = __expf(s0 - ml0);
            ll0 += p0;
            // --- query 1 ---
            if (s1 > ml1) {
                float sc = __expf(ml1 - s1);
                ll1 *= sc;
#pragma unroll
                for (int c = 0; c < CH; c++) acc1[c] *= sc;
                ml1 = s1;
            }
            float p1 = __expf(s1 - ml1);
            ll1 += p1;

#pragma unroll
            for (int c = 0; c < CH; c++) {
                float vv = sV[c][nl];
                acc0[c] += p0 * vv;
                acc1[c] += p1 * vv;
            }
        }
    }

    // cross-lane reductions for both queries
    float gm0 = ml0, gm1 = ml1;
#pragma unroll
    for (int o = 16; o; o >>= 1) {
        gm0 = fmaxf(gm0, __shfl_xor_sync(0xffffffffu, gm0, o));
        gm1 = fmaxf(gm1, __shfl_xor_sync(0xffffffffu, gm1, o));
    }
    float f0 = __expf(ml0 - gm0), f1 = __expf(ml1 - gm1);
    float ls0 = ll0 * f0, ls1 = ll1 * f1;
#pragma unroll
    for (int o = 16; o; o >>= 1) {
        ls0 += __shfl_xor_sync(0xffffffffu, ls0, o);
        ls1 += __shfl_xor_sync(0xffffffffu, ls1, o);
    }
    float inv0 = 1.f / ls0, inv1 = 1.f / ls1;

#pragma unroll
    for (int c = 0; c < CH; c++) {
        float o0 = acc0[c] * f0;
        float o1 = acc1[c] * f1;
#pragma unroll
        for (int q = 16; q; q >>= 1) {
            o0 += __shfl_xor_sync(0xffffffffu, o0, q);
            o1 += __shfl_xor_sync(0xffffffffu, o1, q);
        }
        if (lane == 0) {
            g_outcat[b][vi * C + h * CH + c][m0] = o0 * inv0;
            g_outcat[b][vi * C + h * CH + c][m1] = o1 * inv1;
        }
    }
}

// =====================================================================
// Kernel 5: output projection (unchanged)
// =====================================================================
__global__ __launch_bounds__(256) void k_out(
    const float* __restrict__ ow, const float* __restrict__ ob,
    float* __restrict__ out)
{
    int mm = blockIdx.x * 256 + threadIdx.x;
    int o0 = blockIdx.y * 8;
    int b  = blockIdx.z;

    __shared__ float sW[8][V * C];
    for (int idx = threadIdx.x; idx < 8 * V * C; idx += 256)
        sW[idx / (V * C)][idx % (V * C)] = ow[(o0 + idx / (V * C)) * (V * C) + (idx % (V * C))];
    __syncthreads();

    float acc[8];
#pragma unroll
    for (int oo = 0; oo < 8; oo++) acc[oo] = ob[o0 + oo];

    const float* src = &g_outcat[b][0][0];
    for (int c = 0; c < V * C; c++) {
        float xv = src[c * M + mm];
#pragma unroll
        for (int oo = 0; oo < 8; oo++) acc[oo] += sW[oo][c] * xv;
    }
#pragma unroll
    for (int oo = 0; oo < 8; oo++)
        out[(b * C + o0 + oo) * M + mm] = acc[oo];
}

// =====================================================================
extern "C" void kernel_launch(void* const* d_in, const int* in_sizes, int n_in,
                              void* d_out, int out_size)
{
    const float *x, *query, *refpts, *off_w1, *off_b1, *off_ln_g, *off_ln_b,
                *off_w2, *k_w, *k_b, *v_w, *v_b, *out_w, *out_b, *rpe;

    if (n_in >= 15 && in_sizes[0] == 3145728) {
        x        = (const float*)d_in[0];
        query    = (const float*)d_in[1];
        refpts   = (const float*)d_in[2];
        off_w1   = (const float*)d_in[3];
        off_b1   = (const float*)d_in[4];
        off_ln_g = (const float*)d_in[5];
        off_ln_b = (const float*)d_in[6];
        off_w2   = (const float*)d_in[7];
        k_w      = (const float*)d_in[8];
        k_b      = (const float*)d_in[9];
        v_w      = (const float*)d_in[10];
        v_b      = (const float*)d_in[11];
        out_w    = (const float*)d_in[12];
        out_b    = (const float*)d_in[13];
        rpe      = (const float*)d_in[14];
    } else {
        k_b      = (const float*)d_in[0];
        k_w      = (const float*)d_in[1];
        off_b1   = (const float*)d_in[2];
        off_ln_b = (const float*)d_in[3];
        off_ln_g = (const float*)d_in[4];
        off_w1   = (const float*)d_in[5];
        off_w2   = (const float*)d_in[6];
        out_b    = (const float*)d_in[7];
        out_w    = (const float*)d_in[8];
        query    = (const float*)d_in[9];
        refpts   = (const float*)d_in[10];
        rpe      = (const float*)d_in[11];
        v_b      = (const float*)d_in[12];
        v_w      = (const float*)d_in[13];
        x        = (const float*)d_in[14];
    }
    float* out = (float*)d_out;

    k_offset<<<dim3(M / 256, B * G, V), 256>>>(query, refpts, off_w1, off_b1,
                                               off_ln_g, off_ln_b, off_w2);
    k_sample<<<dim3(NS / 4, B * G, V), 256>>>(x);
    k_proj<<<dim3(NS / 256, C / 8, V * B * 2), 256>>>(k_w, k_b, v_w, v_b);
    k_attn<<<dim3(M / 2 / 8, B * NH, V), 256>>>(query, rpe);
    k_out<<<dim3(M / 256, C / 8, B), 256>>>(out_w, out_b, out);
}